// round 9
// baseline (speedup 1.0000x reference)
#include <cuda_runtime.h>
#include <math.h>
#include <stdint.h>

#define Bsz  64
#define Tlen 256
#define Cdim 384
#define Hn   6
#define Dh   64
#define MTOT (Bsz*Tlen)
#define QKV_ELEMS (Bsz*Hn*Tlen*Dh)   // 6291456

__device__ float g_q[QKV_ELEMS];
__device__ float g_k[QKV_ELEMS];
__device__ float g_v[QKV_ELEMS];
__device__ float g_o[QKV_ELEMS];          // tf32 bit patterns after attn

__device__ uint32_t g_xt[MTOT * Cdim];    // X as tf32
__device__ uint32_t g_wb[3 * Cdim * 384]; // [mat][k][n], n = h*64+d, tf32
__device__ uint32_t g_wpt[Cdim * Cdim];   // [k][n] = Wp[n][k], tf32

// ---------------------------------------------------------------------------
// helpers
// ---------------------------------------------------------------------------
__device__ __forceinline__ uint32_t f2tf(float f) {
    uint32_t r;
    asm("cvt.rna.tf32.f32 %0, %1;" : "=r"(r) : "f"(f));
    return r;
}

__device__ __forceinline__ void mma_tf32(float d[4], const uint32_t a[4],
                                         const uint32_t b[2], const float c[4]) {
    asm volatile(
        "mma.sync.aligned.m16n8k8.row.col.f32.tf32.tf32.f32 "
        "{%0,%1,%2,%3}, {%4,%5,%6,%7}, {%8,%9}, {%10,%11,%12,%13};"
        : "=f"(d[0]), "=f"(d[1]), "=f"(d[2]), "=f"(d[3])
        : "r"(a[0]), "r"(a[1]), "r"(a[2]), "r"(a[3]),
          "r"(b[0]), "r"(b[1]),
          "f"(c[0]), "f"(c[1]), "f"(c[2]), "f"(c[3]));
}

__device__ __forceinline__ void cp16(void* dst, const void* src) {
    uint32_t s = (uint32_t)__cvta_generic_to_shared(dst);
    asm volatile("cp.async.ca.shared.global [%0], [%1], 16;" :: "r"(s), "l"(src));
}
#define CP_COMMIT() asm volatile("cp.async.commit_group;")
#define CP_WAIT1()  asm volatile("cp.async.wait_group 1;")
#define CP_WAIT0()  asm volatile("cp.async.wait_group 0;")

// ---------------------------------------------------------------------------
// Prologue: convert inputs/weights to tf32 once.
// ---------------------------------------------------------------------------
__global__ __launch_bounds__(256) void cvt_x_kernel(const float* __restrict__ X)
{
    int i = blockIdx.x * 256 + threadIdx.x;       // float4 index
    float4 v = ((const float4*)X)[i];
    uint4 u = make_uint4(f2tf(v.x), f2tf(v.y), f2tf(v.z), f2tf(v.w));
    ((uint4*)g_xt)[i] = u;
}

__global__ __launch_bounds__(256) void cvt_w_kernel(
    const float* __restrict__ Wq, const float* __restrict__ Wk,
    const float* __restrict__ Wv, const float* __restrict__ Wp)
{
    int i = blockIdx.x * 256 + threadIdx.x;
    const int NW = 3 * Cdim * 384;
    if (i < NW) {
        int mat = i / (Cdim * 384);
        int rem = i - mat * (Cdim * 384);
        int k = rem / 384, n = rem - (rem / 384) * 384;
        const float* W = (mat == 0) ? Wq : (mat == 1) ? Wk : Wv;
        int h = n >> 6, d = n & 63;
        g_wb[i] = f2tf(W[((size_t)h * Cdim + k) * Dh + d]);
    } else {
        int j = i - NW;                          // [0, 147456)
        int k = j / 384, n = j - k * 384;
        g_wpt[j] = f2tf(Wp[(size_t)n * Cdim + k]);
    }
}

// ---------------------------------------------------------------------------
// QKV projection: cp.async double-buffered tf32 MMA (round-5, known good).
// ---------------------------------------------------------------------------
#define ASTR 36
#define BSTR 136
#define A_WORDS (128 * ASTR)         // 4608
#define B_WORDS (32 * BSTR)          // 4352
#define GEMM_SMEM_BYTES ((2 * A_WORDS + 2 * B_WORDS) * 4)  // 71680

__global__ __launch_bounds__(256, 2) void qkv_mma(void)
{
    extern __shared__ uint32_t dynsm[];
    uint32_t* Asm = dynsm;
    uint32_t* Bsm = dynsm + 2 * A_WORDS;

    const int tid  = threadIdx.x;
    const int lane = tid & 31;
    const int warp = tid >> 5;
    const int gq   = lane >> 2;
    const int tg   = lane & 3;
    const int warpM = (warp >> 2) * 64;
    const int warpN = (warp & 3) * 32;

    const int nbase = blockIdx.x * 128;
    const int mat   = nbase / 384;
    const int nloc  = nbase - mat * 384;
    float* __restrict__ O = (mat == 0) ? g_q : (mat == 1) ? g_k : g_v;
    const int blockM = blockIdx.y * 128;

    const int arow = tid >> 3;            // 0..31
    const int akf  = (tid & 7) * 4;       // 0..28
    const int bk   = tid >> 5;            // 0..7
    const int bnf  = (tid & 31) * 4;      // 0..124

    const uint32_t* __restrict__ wbase = g_wb + (size_t)mat * Cdim * 384 + nloc;

    auto stage = [&](int kt, int buf) {
        uint32_t* A = Asm + buf * A_WORDS;
        uint32_t* B = Bsm + buf * B_WORDS;
        #pragma unroll
        for (int p = 0; p < 4; p++) {
            int m = arow + 32 * p;
            cp16(&A[m * ASTR + akf], &g_xt[(size_t)(blockM + m) * Cdim + kt + akf]);
        }
        #pragma unroll
        for (int p = 0; p < 4; p++) {
            int k = bk + 8 * p;
            cp16(&B[k * BSTR + bnf], &wbase[(size_t)(kt + k) * 384 + bnf]);
        }
    };

    float acc[4][4][4];
    #pragma unroll
    for (int mt = 0; mt < 4; mt++)
        #pragma unroll
        for (int nt = 0; nt < 4; nt++)
            #pragma unroll
            for (int i = 0; i < 4; i++) acc[mt][nt][i] = 0.f;

    stage(0, 0);
    CP_COMMIT();

    const int NK = Cdim / 32;   // 12
    for (int it = 0; it < NK; it++) {
        if (it + 1 < NK) { stage(32 * (it + 1), (it + 1) & 1); CP_COMMIT(); CP_WAIT1(); }
        else            { CP_WAIT0(); }
        __syncthreads();

        const uint32_t* As = Asm + (it & 1) * A_WORDS;
        const uint32_t* Bs = Bsm + (it & 1) * B_WORDS;

        #pragma unroll
        for (int ks = 0; ks < 4; ks++) {
            const int k0 = ks * 8;
            uint32_t a[4][4];
            #pragma unroll
            for (int mt = 0; mt < 4; mt++) {
                int r0 = warpM + mt * 16 + gq;
                a[mt][0] = As[r0 * ASTR + k0 + tg];
                a[mt][1] = As[(r0 + 8) * ASTR + k0 + tg];
                a[mt][2] = As[r0 * ASTR + k0 + tg + 4];
                a[mt][3] = As[(r0 + 8) * ASTR + k0 + tg + 4];
            }
            uint32_t b[4][2];
            #pragma unroll
            for (int nt = 0; nt < 4; nt++) {
                int c0 = warpN + nt * 8 + gq;
                b[nt][0] = Bs[(k0 + tg) * BSTR + c0];
                b[nt][1] = Bs[(k0 + tg + 4) * BSTR + c0];
            }
            #pragma unroll
            for (int mt = 0; mt < 4; mt++)
                #pragma unroll
                for (int nt = 0; nt < 4; nt++)
                    mma_tf32(acc[mt][nt], a[mt], b[nt], acc[mt][nt]);
        }
        __syncthreads();
    }

    #pragma unroll
    for (int mt = 0; mt < 4; mt++) {
        #pragma unroll
        for (int nt = 0; nt < 4; nt++) {
            int cloc = nloc + warpN + nt * 8 + 2 * tg;
            int h = cloc >> 6, d = cloc & 63;
            int r = blockM + warpM + mt * 16 + gq;
            int bb = r >> 8, t = r & 255;
            float2 v0 = make_float2(acc[mt][nt][0], acc[mt][nt][1]);
            *(float2*)&O[(((size_t)bb * Hn + h) * Tlen + t) * Dh + d] = v0;
            float2 v1 = make_float2(acc[mt][nt][2], acc[mt][nt][3]);
            *(float2*)&O[(((size_t)bb * Hn + h) * Tlen + (t + 8)) * Dh + d] = v1;
        }
    }
}

// ---------------------------------------------------------------------------
// Output projection: cp.async double-buffered tf32 MMA (round-5, known good).
// ---------------------------------------------------------------------------
__global__ __launch_bounds__(256, 2) void proj_mma(
    const float* __restrict__ bp,
    float* __restrict__ out)
{
    extern __shared__ uint32_t dynsm[];
    uint32_t* Asm = dynsm;
    uint32_t* Bsm = dynsm + 2 * A_WORDS;

    const int tid  = threadIdx.x;
    const int lane = tid & 31;
    const int warp = tid >> 5;
    const int gq   = lane >> 2;
    const int tg   = lane & 3;
    const int warpM = (warp >> 2) * 64;
    const int warpN = (warp & 3) * 32;

    const int blockN = blockIdx.x * 128;
    const int blockM = blockIdx.y * 128;

    const int arow = tid >> 3;
    const int akf  = (tid & 7) * 4;
    const int bk   = tid >> 5;
    const int bnf  = (tid & 31) * 4;

    auto stage = [&](int kt, int buf) {
        uint32_t* A = Asm + buf * A_WORDS;
        uint32_t* B = Bsm + buf * B_WORDS;
        #pragma unroll
        for (int p = 0; p < 4; p++) {
            int m = arow + 32 * p;
            int mg = blockM + m;
            int kg = kt + akf;
            size_t addr = (((size_t)(mg >> 8)) * Hn + (kg >> 6)) * (Tlen * Dh)
                        + (size_t)(mg & 255) * Dh + (kg & 63);
            cp16(&A[m * ASTR + akf], &g_o[addr]);
        }
        #pragma unroll
        for (int p = 0; p < 4; p++) {
            int k = bk + 8 * p;
            cp16(&B[k * BSTR + bnf], &g_wpt[(size_t)(kt + k) * 384 + blockN + bnf]);
        }
    };

    float acc[4][4][4];
    #pragma unroll
    for (int mt = 0; mt < 4; mt++)
        #pragma unroll
        for (int nt = 0; nt < 4; nt++)
            #pragma unroll
            for (int i = 0; i < 4; i++) acc[mt][nt][i] = 0.f;

    stage(0, 0);
    CP_COMMIT();

    const int NK = Cdim / 32;
    for (int it = 0; it < NK; it++) {
        if (it + 1 < NK) { stage(32 * (it + 1), (it + 1) & 1); CP_COMMIT(); CP_WAIT1(); }
        else            { CP_WAIT0(); }
        __syncthreads();

        const uint32_t* As = Asm + (it & 1) * A_WORDS;
        const uint32_t* Bs = Bsm + (it & 1) * B_WORDS;

        #pragma unroll
        for (int ks = 0; ks < 4; ks++) {
            const int k0 = ks * 8;
            uint32_t a[4][4];
            #pragma unroll
            for (int mt = 0; mt < 4; mt++) {
                int r0 = warpM + mt * 16 + gq;
                a[mt][0] = As[r0 * ASTR + k0 + tg];
                a[mt][1] = As[(r0 + 8) * ASTR + k0 + tg];
                a[mt][2] = As[r0 * ASTR + k0 + tg + 4];
                a[mt][3] = As[(r0 + 8) * ASTR + k0 + tg + 4];
            }
            uint32_t b[4][2];
            #pragma unroll
            for (int nt = 0; nt < 4; nt++) {
                int c0 = warpN + nt * 8 + gq;
                b[nt][0] = Bs[(k0 + tg) * BSTR + c0];
                b[nt][1] = Bs[(k0 + tg + 4) * BSTR + c0];
            }
            #pragma unroll
            for (int mt = 0; mt < 4; mt++)
                #pragma unroll
                for (int nt = 0; nt < 4; nt++)
                    mma_tf32(acc[mt][nt], a[mt], b[nt], acc[mt][nt]);
        }
        __syncthreads();
    }

    #pragma unroll
    for (int mt = 0; mt < 4; mt++) {
        #pragma unroll
        for (int nt = 0; nt < 4; nt++) {
            int n = blockN + warpN + nt * 8 + 2 * tg;
            float b0 = bp[n], b1 = bp[n + 1];
            int r = blockM + warpM + mt * 16 + gq;
            float2 v0 = make_float2(acc[mt][nt][0] + b0, acc[mt][nt][1] + b1);
            *(float2*)&out[(size_t)r * Cdim + n] = v0;
            float2 v1 = make_float2(acc[mt][nt][2] + b0, acc[mt][nt][3] + b1);
            *(float2*)&out[(size_t)(r + 8) * Cdim + n] = v1;
        }
    }
}

// ---------------------------------------------------------------------------
// attn4: 16 warps per CTA, warp w owns rows [16w, 16w+16) of full T=256.
// Q fragments in registers (loaded once from g_q). No Qs buffer, no
// block-level syncs after staging. Causal: warp w runs wrow/64+1 s-blocks.
// ---------------------------------------------------------------------------
#define KTS 264
#define VSS 72
#define PSS 68
#define A4_KT 0
#define A4_VS (A4_KT + 64 * KTS)                // 16896
#define A4_PS (A4_VS + 256 * VSS)               // 35328
#define ATT4_SMEM_WORDS (A4_PS + 256 * PSS)     // 52736
#define ATT4_SMEM_BYTES (ATT4_SMEM_WORDS * 4)   // 210944

__global__ __launch_bounds__(512) void attn4_kernel()
{
    extern __shared__ __align__(16) uint32_t smu[];
    uint32_t* Kt = smu + A4_KT;
    uint32_t* Vs = smu + A4_VS;
    uint32_t* Ps = smu + A4_PS;

    const int bh = blockIdx.x;
    const size_t base = (size_t)bh * (Tlen * Dh);
    const int tid  = threadIdx.x;
    const int lane = tid & 31;
    const int warp = tid >> 5;           // 0..15
    const int gq   = lane >> 2;
    const int tg   = lane & 3;
    const int wrow = warp * 16;

    // --- Stage K transposed: Kt[d][s] ---
    {
        const int s0  = tid & 31;
        const int d4b = tid >> 5;        // 0..15
        #pragma unroll
        for (int it = 0; it < 8; it++) {
            int s  = s0 + 32 * it;
            float4 v = *(const float4*)&g_k[base + (size_t)s * Dh + d4b * 4];
            Kt[(4 * d4b + 0) * KTS + s] = f2tf(v.x);
            Kt[(4 * d4b + 1) * KTS + s] = f2tf(v.y);
            Kt[(4 * d4b + 2) * KTS + s] = f2tf(v.z);
            Kt[(4 * d4b + 3) * KTS + s] = f2tf(v.w);
        }
    }
    // --- Stage V natural: Vs[s][d] ---
    #pragma unroll
    for (int it = 0; it < 8; it++) {
        int idx = tid + 512 * it;        // float4 index, [0,4096)
        int s = idx >> 4, d4 = idx & 15;
        float4 v = *(const float4*)&g_v[base + (size_t)idx * 4];
        uint4 u = make_uint4(f2tf(v.x), f2tf(v.y), f2tf(v.z), f2tf(v.w));
        *(uint4*)&Vs[s * VSS + 4 * d4] = u;
    }

    // --- Q fragments in registers (reused across all s-blocks) ---
    const int row0 = wrow + gq;
    const int row1 = row0 + 8;
    uint32_t qfr[8][4];
    {
        const float* q0 = &g_q[base + (size_t)row0 * Dh];
        const float* q1 = &g_q[base + (size_t)row1 * Dh];
        #pragma unroll
        for (int ks = 0; ks < 8; ks++) {
            const int kk = ks * 8;
            qfr[ks][0] = f2tf(q0[kk + tg]);
            qfr[ks][1] = f2tf(q1[kk + tg]);
            qfr[ks][2] = f2tf(q0[kk + tg + 4]);
            qfr[ks][3] = f2tf(q1[kk + tg + 4]);
        }
    }
    __syncthreads();

    const float scale = 0.125f;

    float m0r = -INFINITY, m1r = -INFINITY;
    float l0 = 0.f, l1 = 0.f;
    float o[8][4];
    #pragma unroll
    for (int nt = 0; nt < 8; nt++)
        #pragma unroll
        for (int c = 0; c < 4; c++) o[nt][c] = 0.f;

    const int nblocks = (wrow >> 6) + 1;       // 1..4, warp-uniform
    for (int sb = 0; sb < nblocks; sb++) {

        // ---- S = Q K^T (16 rows x 64 cols) ----
        float sacc[8][4];
        #pragma unroll
        for (int nt = 0; nt < 8; nt++)
            #pragma unroll
            for (int c = 0; c < 4; c++) sacc[nt][c] = 0.f;

        #pragma unroll
        for (int ks = 0; ks < 8; ks++) {
            const int kk = ks * 8;
            #pragma unroll
            for (int nt = 0; nt < 8; nt++) {
                uint32_t b[2];
                const int cc = sb * 64 + nt * 8 + gq;
                b[0] = Kt[(kk + tg) * KTS + cc];
                b[1] = Kt[(kk + tg + 4) * KTS + cc];
                mma_tf32(sacc[nt], qfr[ks], b, sacc[nt]);
            }
        }

        // ---- mask + online softmax ----
        float bm0 = -INFINITY, bm1 = -INFINITY;
        #pragma unroll
        for (int nt = 0; nt < 8; nt++) {
            const int c0 = sb * 64 + nt * 8 + 2 * tg;
            float v00 = (c0     <= row0) ? sacc[nt][0] * scale : -INFINITY;
            float v01 = (c0 + 1 <= row0) ? sacc[nt][1] * scale : -INFINITY;
            float v10 = (c0     <= row1) ? sacc[nt][2] * scale : -INFINITY;
            float v11 = (c0 + 1 <= row1) ? sacc[nt][3] * scale : -INFINITY;
            sacc[nt][0] = v00; sacc[nt][1] = v01;
            sacc[nt][2] = v10; sacc[nt][3] = v11;
            bm0 = fmaxf(bm0, fmaxf(v00, v01));
            bm1 = fmaxf(bm1, fmaxf(v10, v11));
        }
        bm0 = fmaxf(bm0, __shfl_xor_sync(0xffffffffu, bm0, 1));
        bm0 = fmaxf(bm0, __shfl_xor_sync(0xffffffffu, bm0, 2));
        bm1 = fmaxf(bm1, __shfl_xor_sync(0xffffffffu, bm1, 1));
        bm1 = fmaxf(bm1, __shfl_xor_sync(0xffffffffu, bm1, 2));

        const float mn0 = fmaxf(m0r, bm0);
        const float mn1 = fmaxf(m1r, bm1);
        const float cor0 = __expf(m0r - mn0);
        const float cor1 = __expf(m1r - mn1);
        m0r = mn0; m1r = mn1;

        float rs0 = 0.f, rs1 = 0.f;
        #pragma unroll
        for (int nt = 0; nt < 8; nt++) {
            float p00 = __expf(sacc[nt][0] - mn0);
            float p01 = __expf(sacc[nt][1] - mn0);
            float p10 = __expf(sacc[nt][2] - mn1);
            float p11 = __expf(sacc[nt][3] - mn1);
            rs0 += p00 + p01;
            rs1 += p10 + p11;
            uint2 u0 = make_uint2(f2tf(p00), f2tf(p01));
            *(uint2*)&Ps[(wrow + gq) * PSS + nt * 8 + 2 * tg] = u0;
            uint2 u1 = make_uint2(f2tf(p10), f2tf(p11));
            *(uint2*)&Ps[(wrow + gq + 8) * PSS + nt * 8 + 2 * tg] = u1;
        }
        rs0 += __shfl_xor_sync(0xffffffffu, rs0, 1);
        rs0 += __shfl_xor_sync(0xffffffffu, rs0, 2);
        rs1 += __shfl_xor_sync(0xffffffffu, rs1, 1);
        rs1 += __shfl_xor_sync(0xffffffffu, rs1, 2);
        l0 = l0 * cor0 + rs0;
        l1 = l1 * cor1 + rs1;

        #pragma unroll
        for (int nt = 0; nt < 8; nt++) {
            o[nt][0] *= cor0; o[nt][1] *= cor0;
            o[nt][2] *= cor1; o[nt][3] *= cor1;
        }
        __syncwarp();

        // ---- O += P V ----
        #pragma unroll
        for (int ks = 0; ks < 8; ks++) {
            const int kk = ks * 8;
            uint32_t a[4];
            a[0] = Ps[(wrow + gq) * PSS + kk + tg];
            a[1] = Ps[(wrow + gq + 8) * PSS + kk + tg];
            a[2] = Ps[(wrow + gq) * PSS + kk + tg + 4];
            a[3] = Ps[(wrow + gq + 8) * PSS + kk + tg + 4];
            #pragma unroll
            for (int nt = 0; nt < 8; nt++) {
                uint32_t b[2];
                b[0] = Vs[(sb * 64 + kk + tg) * VSS + nt * 8 + gq];
                b[1] = Vs[(sb * 64 + kk + tg + 4) * VSS + nt * 8 + gq];
                mma_tf32(o[nt], a, b, o[nt]);
            }
        }
        __syncwarp();   // Ps rows are warp-private; order WAR for next sb
    }

    // ---- finalize: write tf32 bit patterns (consumed by proj_mma cp.async) ----
    const float inv0 = 1.0f / l0;
    const float inv1 = 1.0f / l1;
    #pragma unroll
    for (int nt = 0; nt < 8; nt++) {
        const int col = nt * 8 + 2 * tg;
        float2 v0 = make_float2(__uint_as_float(f2tf(o[nt][0] * inv0)),
                                __uint_as_float(f2tf(o[nt][1] * inv0)));
        *(float2*)&g_o[base + (size_t)row0 * Dh + col] = v0;
        float2 v1 = make_float2(__uint_as_float(f2tf(o[nt][2] * inv1)),
                                __uint_as_float(f2tf(o[nt][3] * inv1)));
        *(float2*)&g_o[base + (size_t)row1 * Dh + col] = v1;
    }
}

// ---------------------------------------------------------------------------
extern "C" void kernel_launch(void* const* d_in, const int* in_sizes, int n_in,
                              void* d_out, int out_size)
{
    const float* x  = (const float*)d_in[0];
    const float* Wq = (const float*)d_in[1];
    const float* Wk = (const float*)d_in[2];
    const float* Wv = (const float*)d_in[3];
    const float* Wp = (const float*)d_in[4];
    const float* bp = (const float*)d_in[5];
    float* out = (float*)d_out;

    (void)in_sizes; (void)n_in; (void)out_size;

    cudaFuncSetAttribute(qkv_mma,
                         cudaFuncAttributeMaxDynamicSharedMemorySize, GEMM_SMEM_BYTES);
    cudaFuncSetAttribute(proj_mma,
                         cudaFuncAttributeMaxDynamicSharedMemorySize, GEMM_SMEM_BYTES);
    cudaFuncSetAttribute(attn4_kernel,
                         cudaFuncAttributeMaxDynamicSharedMemorySize, ATT4_SMEM_BYTES);

    cvt_x_kernel<<<(MTOT * Cdim / 4) / 256, 256>>>(x);
    cvt_w_kernel<<<(4 * Cdim * 384) / 256, 256>>>(Wq, Wk, Wv, Wp);
    qkv_mma<<<dim3(9, 128), 256, GEMM_SMEM_BYTES>>>();
    attn4_kernel<<<dim3(Bsz * Hn), 512, ATT4_SMEM_BYTES>>>();
    proj_mma<<<dim3(3, 128), 256, GEMM_SMEM_BYTES>>>(bp, out);
}